// round 14
// baseline (speedup 1.0000x reference)
#include <cuda_runtime.h>
#include <cuda_fp16.h>
#include <math.h>

#define N_MAX 100000
#define E_MAX 3200000
#define SCAN_TPB 512
#define SCAN_NB ((N_MAX + SCAN_TPB - 1) / SCAN_TPB)

// ---- device scratch (allocation-free rule: static globals) ----
__device__ int            g_deg[N_MAX];
__device__ int            g_off[N_MAX + 1];
__device__ float          g_dinv[N_MAX];
__device__ float          g_t0[N_MAX];
__device__ unsigned char  g_rank[E_MAX];    // per-edge rank within its dst (Poisson(32): max << 256)
__device__ int            g_srcs[E_MAX];
__device__ __half2        g_t1[N_MAX * 8];  // fp16 t1: 16 halves/node (32 B/row)
__device__ float4         g_bufB[N_MAX * 16]; // fp32: g (d16) and t4 stage (d5 pad8)
__device__ __half2        g_bufH[N_MAX * 32]; // fp16 t3: 64 halves/node (128 B/row)
__device__ unsigned long long g_pack[SCAN_NB]; // decoupled-lookback: bit63 flag | low32 sum

// accumulate a uint4 of 8 halves into fp32 acc[8]
__device__ __forceinline__ void hacc8(float* acc, uint4 hv) {
    float2 f0 = __half22float2(*(const __half2*)&hv.x);
    float2 f1 = __half22float2(*(const __half2*)&hv.y);
    float2 f2 = __half22float2(*(const __half2*)&hv.z);
    float2 f3 = __half22float2(*(const __half2*)&hv.w);
    acc[0] += f0.x; acc[1] += f0.y; acc[2] += f1.x; acc[3] += f1.y;
    acc[4] += f2.x; acc[5] += f2.y; acc[6] += f3.x; acc[7] += f3.y;
}

// accumulate a uint2 of 4 halves into fp32 acc[4]
__device__ __forceinline__ void hacc4(float* acc, uint2 hv) {
    float2 f0 = __half22float2(*(const __half2*)&hv.x);
    float2 f1 = __half22float2(*(const __half2*)&hv.y);
    acc[0] += f0.x; acc[1] += f0.y; acc[2] += f1.x; acc[3] += f1.y;
}

// ---------------- CSR build ----------------
__global__ void k_zero(int n) {
    int i = blockIdx.x * blockDim.x + threadIdx.x;
    if (i < n) g_deg[i] = 0;
    if (i < SCAN_NB) g_pack[i] = 0ULL;
}

// count + record rank of each edge within its dst
__global__ void k_count(const int* __restrict__ ei, int E) {
    int e = blockIdx.x * blockDim.x + threadIdx.x;
    if (e < E) g_rank[e] = (unsigned char)atomicAdd(&g_deg[ei[E + e]], 1);
}

// vectorized: 4 dsts per thread (requires E % 4 == 0); ei pre-offset to dst half
__global__ void k_count4(const int* __restrict__ ei, int E4) {
    int e = blockIdx.x * blockDim.x + threadIdx.x;
    if (e < E4) {
        int4 d = ((const int4*)ei)[e];
        unsigned char r0 = (unsigned char)atomicAdd(&g_deg[d.x], 1);
        unsigned char r1 = (unsigned char)atomicAdd(&g_deg[d.y], 1);
        unsigned char r2 = (unsigned char)atomicAdd(&g_deg[d.z], 1);
        unsigned char r3 = (unsigned char)atomicAdd(&g_deg[d.w], 1);
        ((uchar4*)g_rank)[e] = make_uchar4(r0, r1, r2, r3);
    }
}

// ---- fused single-pass exclusive scan (decoupled lookback) + dinv + t0 ----
__global__ __launch_bounds__(SCAN_TPB) void k_scanf(const float* __restrict__ x, int n, int E) {
    __shared__ int sd[SCAN_TPB];
    int t = threadIdx.x;
    int b = blockIdx.x;
    int i = b * SCAN_TPB + t;
    int v = (i < n) ? g_deg[i] : 0;
    sd[t] = v;
    __syncthreads();
    for (int off = 1; off < SCAN_TPB; off <<= 1) {
        int y = (t >= off) ? sd[t - off] : 0;
        __syncthreads();
        sd[t] += y;
        __syncthreads();
    }
    int incl = sd[t];
    if (t == SCAN_TPB - 1) {
        unsigned long long p = (1ULL << 63) | (unsigned long long)(unsigned)incl;
        *((volatile unsigned long long*)&g_pack[b]) = p;
    }
    int offs = 0;
    for (int p = t; p < b; p += SCAN_TPB) {
        unsigned long long w;
        do { w = *((volatile unsigned long long*)&g_pack[p]); } while (!(w >> 63));
        offs += (int)(unsigned)(w & 0xFFFFFFFFULL);
    }
    __syncthreads();
    sd[t] = offs;
    __syncthreads();
    for (int o = SCAN_TPB / 2; o > 0; o >>= 1) {
        if (t < o) sd[t] += sd[t + o];
        __syncthreads();
    }
    int blockoff = sd[0];
    if (i < n) {
        int off = blockoff + incl - v;
        g_off[i] = off;
        float dv = rsqrtf((float)(v + 1));  // +1 self loop
        g_dinv[i] = dv;
        g_t0[i] = x[i] * dv;
        if (i == 0) g_off[n] = E;
    }
}

// atomic-free fill: p = off[d] + rank[e]
__global__ void k_fill(const int* __restrict__ ei, int E) {
    int e = blockIdx.x * blockDim.x + threadIdx.x;
    if (e < E) {
        int s = ei[e];
        int d = ei[E + e];
        g_srcs[__ldg(&g_off[d]) + (int)g_rank[e]] = s;
    }
}

// vectorized: 4 edges per thread (requires E % 4 == 0)
__global__ void k_fill4(const int* __restrict__ ei, int E, int E4) {
    int e = blockIdx.x * blockDim.x + threadIdx.x;
    if (e < E4) {
        int4 s = ((const int4*)ei)[e];
        int4 d = ((const int4*)(ei + E))[e];
        uchar4 r = ((const uchar4*)g_rank)[e];
        g_srcs[__ldg(&g_off[d.x]) + (int)r.x] = s.x;
        g_srcs[__ldg(&g_off[d.y]) + (int)r.y] = s.y;
        g_srcs[__ldg(&g_off[d.z]) + (int)r.z] = s.z;
        g_srcs[__ldg(&g_off[d.w]) + (int)r.w] = s.w;
    }
}

// ---------------- layer 1: scalar agg of t0 (batch-8 MLP), then t1 = fp16(dinv*relu(a*W1+b1)) ----------------
__global__ void k_l1(const float* __restrict__ W1, const float* __restrict__ b1, int n) {
    __shared__ float sw[16], sb[16];
    if (threadIdx.x < 16) { sw[threadIdx.x] = W1[threadIdx.x]; sb[threadIdx.x] = b1[threadIdx.x]; }
    __syncthreads();
    int v = blockIdx.x * blockDim.x + threadIdx.x;
    if (v >= n) return;
    float a = g_t0[v];
    int e = g_off[v], e1 = g_off[v + 1];
    for (; e + 8 <= e1; e += 8) {
        int s0 = __ldg(&g_srcs[e + 0]);
        int s1 = __ldg(&g_srcs[e + 1]);
        int s2 = __ldg(&g_srcs[e + 2]);
        int s3 = __ldg(&g_srcs[e + 3]);
        int s4 = __ldg(&g_srcs[e + 4]);
        int s5 = __ldg(&g_srcs[e + 5]);
        int s6 = __ldg(&g_srcs[e + 6]);
        int s7 = __ldg(&g_srcs[e + 7]);
        float f0 = __ldg(&g_t0[s0]);
        float f1 = __ldg(&g_t0[s1]);
        float f2 = __ldg(&g_t0[s2]);
        float f3 = __ldg(&g_t0[s3]);
        float f4 = __ldg(&g_t0[s4]);
        float f5 = __ldg(&g_t0[s5]);
        float f6 = __ldg(&g_t0[s6]);
        float f7 = __ldg(&g_t0[s7]);
        a += ((f0 + f1) + (f2 + f3)) + ((f4 + f5) + (f6 + f7));
    }
    for (; e < e1; e++) a += __ldg(&g_t0[__ldg(&g_srcs[e])]);
    float dv = g_dinv[v];
    a *= dv;
#pragma unroll
    for (int k = 0; k < 8; k++) {
        float u0 = dv * fmaxf(fmaf(a, sw[2 * k + 0], sb[2 * k + 0]), 0.f);
        float u1 = dv * fmaxf(fmaf(a, sw[2 * k + 1], sb[2 * k + 1]), 0.f);
        g_t1[v * 8 + k] = __float22half2_rn(make_float2(u0, u1));
    }
}

// ---------------- layer-2 agg d16 fp16, batch-8 MLP: g = dinv*(t1[v] + sum t1[src]) -> bufB fp32 ----------------
__global__ void k_agg2(int n) {
    int gid = blockIdx.x * blockDim.x + threadIdx.x;
    int v = gid >> 1;
    int c = gid & 1;
    if (v >= n) return;
    const uint4* tp = (const uint4*)g_t1;
    float acc[8];
    {
        uint4 hv = tp[v * 2 + c];
        float2 f0 = __half22float2(*(const __half2*)&hv.x);
        float2 f1 = __half22float2(*(const __half2*)&hv.y);
        float2 f2 = __half22float2(*(const __half2*)&hv.z);
        float2 f3 = __half22float2(*(const __half2*)&hv.w);
        acc[0] = f0.x; acc[1] = f0.y; acc[2] = f1.x; acc[3] = f1.y;
        acc[4] = f2.x; acc[5] = f2.y; acc[6] = f3.x; acc[7] = f3.y;
    }
    int e = g_off[v], e1 = g_off[v + 1];
    for (; e + 8 <= e1; e += 8) {
        int s0 = __ldg(&g_srcs[e + 0]);
        int s1 = __ldg(&g_srcs[e + 1]);
        int s2 = __ldg(&g_srcs[e + 2]);
        int s3 = __ldg(&g_srcs[e + 3]);
        int s4 = __ldg(&g_srcs[e + 4]);
        int s5 = __ldg(&g_srcs[e + 5]);
        int s6 = __ldg(&g_srcs[e + 6]);
        int s7 = __ldg(&g_srcs[e + 7]);
        uint4 a0 = __ldg(&tp[s0 * 2 + c]);
        uint4 a1 = __ldg(&tp[s1 * 2 + c]);
        uint4 a2 = __ldg(&tp[s2 * 2 + c]);
        uint4 a3 = __ldg(&tp[s3 * 2 + c]);
        uint4 a4 = __ldg(&tp[s4 * 2 + c]);
        uint4 a5 = __ldg(&tp[s5 * 2 + c]);
        uint4 a6 = __ldg(&tp[s6 * 2 + c]);
        uint4 a7 = __ldg(&tp[s7 * 2 + c]);
        hacc8(acc, a0); hacc8(acc, a1); hacc8(acc, a2); hacc8(acc, a3);
        hacc8(acc, a4); hacc8(acc, a5); hacc8(acc, a6); hacc8(acc, a7);
    }
    for (; e < e1; e++) {
        int s = __ldg(&g_srcs[e]);
        hacc8(acc, __ldg(&tp[s * 2 + c]));
    }
    float dv = g_dinv[v];
    g_bufB[v * 4 + c * 2 + 0] = make_float4(acc[0] * dv, acc[1] * dv, acc[2] * dv, acc[3] * dv);
    g_bufB[v * 4 + c * 2 + 1] = make_float4(acc[4] * dv, acc[5] * dv, acc[6] * dv, acc[7] * dv);
}

// ---------------- fused W2 + relu + W3 + dinv, HFMA2 W3 stage: g(d16) -> t3(d64 fp16) ----------------
__global__ __launch_bounds__(128) void k_t23(const float* __restrict__ W2,
                                             const float* __restrict__ b2,
                                             const float* __restrict__ W3, int n) {
    __shared__ float   sW2[16 * 64];
    __shared__ __half2 sW3h[64 * 32];   // [i][jp]: (W3[i][2jp], W3[i][2jp+1]); 8 KB
    __shared__ float   sb2[64];
    int t = threadIdx.x;
    for (int i = t; i < 16 * 64; i += blockDim.x) sW2[i] = W2[i];
    for (int idx = t; idx < 64 * 32; idx += blockDim.x) {
        int i = idx >> 5, jp = idx & 31;
        sW3h[idx] = __floats2half2_rn(W3[i * 64 + 2 * jp], W3[i * 64 + 2 * jp + 1]);
    }
    if (t < 64) sb2[t] = b2[t];
    __syncthreads();
    int v = blockIdx.x * blockDim.x + t;
    if (v >= n) return;
    float g[16];
#pragma unroll
    for (int j = 0; j < 4; j++) {
        float4 gg = g_bufB[v * 4 + j];
        g[4 * j] = gg.x; g[4 * j + 1] = gg.y; g[4 * j + 2] = gg.z; g[4 * j + 3] = gg.w;
    }
    float2 zf[32];
#pragma unroll
    for (int j = 0; j < 32; j++) zf[j] = make_float2(0.f, 0.f);
#pragma unroll
    for (int ch = 0; ch < 4; ch++) {
        float4 a[4];
#pragma unroll
        for (int q = 0; q < 4; q++) a[q] = ((const float4*)sb2)[ch * 4 + q];
#pragma unroll
        for (int k = 0; k < 16; k++) {
            float gk = g[k];
            const float4* wk = (const float4*)&sW2[k * 64 + ch * 16];
#pragma unroll
            for (int q = 0; q < 4; q++) {
                float4 w = wk[q];
                a[q].x = fmaf(gk, w.x, a[q].x); a[q].y = fmaf(gk, w.y, a[q].y);
                a[q].z = fmaf(gk, w.z, a[q].z); a[q].w = fmaf(gk, w.w, a[q].w);
            }
        }
        __half2 yb[16];
#pragma unroll
        for (int q = 0; q < 4; q++) {
            yb[4 * q + 0] = __float2half2_rn(fmaxf(a[q].x, 0.f));
            yb[4 * q + 1] = __float2half2_rn(fmaxf(a[q].y, 0.f));
            yb[4 * q + 2] = __float2half2_rn(fmaxf(a[q].z, 0.f));
            yb[4 * q + 3] = __float2half2_rn(fmaxf(a[q].w, 0.f));
        }
        __half2 zh[32];
        __half2 hz = __float2half2_rn(0.f);
#pragma unroll
        for (int j = 0; j < 32; j++) zh[j] = hz;
#pragma unroll
        for (int ii = 0; ii < 16; ii++) {
            const uint4* wr4 = (const uint4*)&sW3h[(ch * 16 + ii) * 32];
            __half2 yv = yb[ii];
#pragma unroll
            for (int jq = 0; jq < 8; jq++) {
                uint4 w = wr4[jq];
                zh[jq * 4 + 0] = __hfma2(yv, *(const __half2*)&w.x, zh[jq * 4 + 0]);
                zh[jq * 4 + 1] = __hfma2(yv, *(const __half2*)&w.y, zh[jq * 4 + 1]);
                zh[jq * 4 + 2] = __hfma2(yv, *(const __half2*)&w.z, zh[jq * 4 + 2]);
                zh[jq * 4 + 3] = __hfma2(yv, *(const __half2*)&w.w, zh[jq * 4 + 3]);
            }
        }
#pragma unroll
        for (int j = 0; j < 32; j++) {
            float2 f = __half22float2(zh[j]);
            zf[j].x += f.x; zf[j].y += f.y;
        }
    }
    float dv = g_dinv[v];
#pragma unroll
    for (int j = 0; j < 32; j++)
        g_bufH[v * 32 + j] = __float22half2_rn(make_float2(zf[j].x * dv, zf[j].y * dv));
}

// ---------------- d=64 fp16 agg, 16 lanes/node (8B uint2/lane), batch-8 MLP + b3/relu/W4 epilogue ----------------
__global__ void k_agg3w4(const float* __restrict__ b3, const float* __restrict__ W4, int n) {
    __shared__ float sW4[64 * 5];
    int t = threadIdx.x;
    for (int i = t; i < 64 * 5; i += blockDim.x) sW4[i] = W4[i];
    __syncthreads();
    int gid = blockIdx.x * blockDim.x + t;
    int v = gid / 16;
    int c = gid % 16;
    if (v >= n) return;

    const uint2* hp = (const uint2*)g_bufH;   // 16 uint2 per node row (128 B)
    float acc[4];
    {
        uint2 hv = hp[v * 16 + c];            // self-loop term
        float2 f0 = __half22float2(*(const __half2*)&hv.x);
        float2 f1 = __half22float2(*(const __half2*)&hv.y);
        acc[0] = f0.x; acc[1] = f0.y; acc[2] = f1.x; acc[3] = f1.y;
    }
    int e = g_off[v], e1 = g_off[v + 1];
    for (; e + 8 <= e1; e += 8) {
        int s0 = __ldg(&g_srcs[e + 0]);
        int s1 = __ldg(&g_srcs[e + 1]);
        int s2 = __ldg(&g_srcs[e + 2]);
        int s3 = __ldg(&g_srcs[e + 3]);
        int s4 = __ldg(&g_srcs[e + 4]);
        int s5 = __ldg(&g_srcs[e + 5]);
        int s6 = __ldg(&g_srcs[e + 6]);
        int s7 = __ldg(&g_srcs[e + 7]);
        uint2 a0 = __ldg(&hp[s0 * 16 + c]);
        uint2 a1 = __ldg(&hp[s1 * 16 + c]);
        uint2 a2 = __ldg(&hp[s2 * 16 + c]);
        uint2 a3 = __ldg(&hp[s3 * 16 + c]);
        uint2 a4 = __ldg(&hp[s4 * 16 + c]);
        uint2 a5 = __ldg(&hp[s5 * 16 + c]);
        uint2 a6 = __ldg(&hp[s6 * 16 + c]);
        uint2 a7 = __ldg(&hp[s7 * 16 + c]);
        hacc4(acc, a0); hacc4(acc, a1); hacc4(acc, a2); hacc4(acc, a3);
        hacc4(acc, a4); hacc4(acc, a5); hacc4(acc, a6); hacc4(acc, a7);
    }
    for (; e < e1; e++) {
        int s = __ldg(&g_srcs[e]);
        hacc4(acc, __ldg(&hp[s * 16 + c]));
    }
    float dv = g_dinv[v];
    float4 bb = ((const float4*)b3)[c];
    float h[4];
    h[0] = fmaxf(fmaf(acc[0], dv, bb.x), 0.f);
    h[1] = fmaxf(fmaf(acc[1], dv, bb.y), 0.f);
    h[2] = fmaxf(fmaf(acc[2], dv, bb.z), 0.f);
    h[3] = fmaxf(fmaf(acc[3], dv, bb.w), 0.f);
    const float* w = &sW4[c * 4 * 5];
    float p[5];
#pragma unroll
    for (int j = 0; j < 5; j++)
        p[j] = fmaf(h[0], w[j], fmaf(h[1], w[5 + j], fmaf(h[2], w[10 + j], h[3] * w[15 + j])));
    unsigned m = __activemask();
#pragma unroll
    for (int off = 8; off > 0; off >>= 1) {
#pragma unroll
        for (int j = 0; j < 5; j++) p[j] += __shfl_down_sync(m, p[j], off, 16);
    }
    if (c == 0) {
        g_bufB[v * 2 + 0] = make_float4(dv * p[0], dv * p[1], dv * p[2], dv * p[3]);
        g_bufB[v * 2 + 1] = make_float4(dv * p[4], 0.f, 0.f, 0.f);
    }
}

// ---------------- final d=5 agg (batch-4 MLP) + b4 + log_softmax ----------------
__global__ void k_final(const float* __restrict__ b4, float* __restrict__ out, int n) {
    int v = blockIdx.x * blockDim.x + threadIdx.x;
    if (v >= n) return;
    float4 a0 = g_bufB[v * 2 + 0];
    float4 a1 = g_bufB[v * 2 + 1];
    int e = g_off[v], e1 = g_off[v + 1];
    for (; e + 4 <= e1; e += 4) {
        int s0 = __ldg(&g_srcs[e + 0]);
        int s1 = __ldg(&g_srcs[e + 1]);
        int s2 = __ldg(&g_srcs[e + 2]);
        int s3 = __ldg(&g_srcs[e + 3]);
        float4 p00 = __ldg(&g_bufB[s0 * 2 + 0]);
        float4 p01 = __ldg(&g_bufB[s0 * 2 + 1]);
        float4 p10 = __ldg(&g_bufB[s1 * 2 + 0]);
        float4 p11 = __ldg(&g_bufB[s1 * 2 + 1]);
        float4 p20 = __ldg(&g_bufB[s2 * 2 + 0]);
        float4 p21 = __ldg(&g_bufB[s2 * 2 + 1]);
        float4 p30 = __ldg(&g_bufB[s3 * 2 + 0]);
        float4 p31 = __ldg(&g_bufB[s3 * 2 + 1]);
        a0.x += (p00.x + p10.x) + (p20.x + p30.x);
        a0.y += (p00.y + p10.y) + (p20.y + p30.y);
        a0.z += (p00.z + p10.z) + (p20.z + p30.z);
        a0.w += (p00.w + p10.w) + (p20.w + p30.w);
        a1.x += (p01.x + p11.x) + (p21.x + p31.x);
    }
    for (; e < e1; e++) {
        int s = __ldg(&g_srcs[e]);
        float4 t0 = __ldg(&g_bufB[s * 2 + 0]);
        float4 t1 = __ldg(&g_bufB[s * 2 + 1]);
        a0.x += t0.x; a0.y += t0.y; a0.z += t0.z; a0.w += t0.w;
        a1.x += t1.x;
    }
    float dv = g_dinv[v];
    float z[5];
    z[0] = fmaf(a0.x, dv, b4[0]);
    z[1] = fmaf(a0.y, dv, b4[1]);
    z[2] = fmaf(a0.z, dv, b4[2]);
    z[3] = fmaf(a0.w, dv, b4[3]);
    z[4] = fmaf(a1.x, dv, b4[4]);
    float mx = z[0];
#pragma unroll
    for (int j = 1; j < 5; j++) mx = fmaxf(mx, z[j]);
    float sum = 0.f;
#pragma unroll
    for (int j = 0; j < 5; j++) sum += expf(z[j] - mx);
    float l = mx + logf(sum);
#pragma unroll
    for (int j = 0; j < 5; j++) out[v * 5 + j] = z[j] - l;
}

extern "C" void kernel_launch(void* const* d_in, const int* in_sizes, int n_in,
                              void* d_out, int out_size) {
    const float* x  = (const float*)d_in[0];
    const int*   ei = (const int*)d_in[1];      // int32 (JAX x64 disabled)
    const float* W1 = (const float*)d_in[2];
    const float* b1 = (const float*)d_in[3];
    const float* W2 = (const float*)d_in[4];
    const float* b2 = (const float*)d_in[5];
    const float* W3 = (const float*)d_in[6];
    const float* b3 = (const float*)d_in[7];
    const float* W4 = (const float*)d_in[8];
    const float* b4 = (const float*)d_in[9];
    float* out = (float*)d_out;

    int N = in_sizes[0];
    int E = in_sizes[1] / 2;

    int nB  = (N + 255) / 256;
    int snb = (N + SCAN_TPB - 1) / SCAN_TPB;

    // CSR build: zero -> count(+uchar rank) -> fused scan -> atomic-free fill
    k_zero<<<nB, 256>>>(N);
    if ((E & 3) == 0) {
        int E4 = E >> 2;
        int eB4 = (E4 + 255) / 256;
        k_count4<<<eB4, 256>>>(ei + E, E4);
        k_scanf<<<snb, SCAN_TPB>>>(x, N, E);
        k_fill4<<<eB4, 256>>>(ei, E, E4);
    } else {
        int eB = (E + 255) / 256;
        k_count<<<eB, 256>>>(ei, E);
        k_scanf<<<snb, SCAN_TPB>>>(x, N, E);
        k_fill<<<eB, 256>>>(ei, E);
    }

    // Layer 1: scalar agg (batch-8) + transform (1->16), fp16 out
    k_l1<<<nB, 256>>>(W1, b1, N);
    // Layer 2 agg in d=16 fp16 (before W2), batch-8 MLP
    k_agg2<<<(N * 2 + 255) / 256, 256>>>(N);
    // Fused W2+relu+W3 node transform (HFMA2 W3 stage)
    k_t23<<<(N + 127) / 128, 128>>>(W2, b2, W3, N);
    // Layer 3 agg d=64 fp16, 16 lanes/node (batch-8 MLP), fused bias/relu/W4 epilogue
    k_agg3w4<<<(N * 16 + 255) / 256, 256>>>(b3, W4, N);
    // Layer 4 agg d=5 (batch-4) + log_softmax
    k_final<<<nB, 256>>>(b4, out, N);
}

// round 15
// speedup vs baseline: 1.0671x; 1.0671x over previous
#include <cuda_runtime.h>
#include <cuda_fp16.h>
#include <cuda_fp8.h>
#include <math.h>

#define N_MAX 100000
#define E_MAX 3200000
#define SCAN_TPB 512
#define SCAN_NB ((N_MAX + SCAN_TPB - 1) / SCAN_TPB)

// ---- device scratch (allocation-free rule: static globals) ----
__device__ int            g_deg[N_MAX];
__device__ int            g_off[N_MAX + 1];
__device__ float          g_dinv[N_MAX];
__device__ float          g_t0[N_MAX];
__device__ unsigned char  g_rank[E_MAX];    // per-edge rank within its dst (Poisson(32): max << 256)
__device__ int            g_srcs[E_MAX];
__device__ __half2        g_t1[N_MAX * 8];  // fp16 t1: 16 halves/node (32 B/row)
__device__ float4         g_bufB[N_MAX * 16]; // fp32: g (d16) and t4 stage (d5 pad8)
__device__ unsigned int   g_bufF[N_MAX * 16]; // fp8 t3: 64 e4m3/node (64 B/row, 16 uints)
__device__ unsigned long long g_pack[SCAN_NB]; // decoupled-lookback: bit63 flag | low32 sum

// accumulate a uint4 of 8 halves into fp32 acc[8]
__device__ __forceinline__ void hacc8(float* acc, uint4 hv) {
    float2 f0 = __half22float2(*(const __half2*)&hv.x);
    float2 f1 = __half22float2(*(const __half2*)&hv.y);
    float2 f2 = __half22float2(*(const __half2*)&hv.z);
    float2 f3 = __half22float2(*(const __half2*)&hv.w);
    acc[0] += f0.x; acc[1] += f0.y; acc[2] += f1.x; acc[3] += f1.y;
    acc[4] += f2.x; acc[5] += f2.y; acc[6] += f3.x; acc[7] += f3.y;
}

// accumulate a uint2 of 8 e4m3 values into fp32 acc[8]
__device__ __forceinline__ void facc8(float* acc, uint2 hv) {
    __half2_raw h0 = __nv_cvt_fp8x2_to_halfraw2((__nv_fp8x2_storage_t)(hv.x & 0xFFFF), __NV_E4M3);
    __half2_raw h1 = __nv_cvt_fp8x2_to_halfraw2((__nv_fp8x2_storage_t)(hv.x >> 16),    __NV_E4M3);
    __half2_raw h2 = __nv_cvt_fp8x2_to_halfraw2((__nv_fp8x2_storage_t)(hv.y & 0xFFFF), __NV_E4M3);
    __half2_raw h3 = __nv_cvt_fp8x2_to_halfraw2((__nv_fp8x2_storage_t)(hv.y >> 16),    __NV_E4M3);
    float2 f0 = __half22float2(*(const __half2*)&h0);
    float2 f1 = __half22float2(*(const __half2*)&h1);
    float2 f2 = __half22float2(*(const __half2*)&h2);
    float2 f3 = __half22float2(*(const __half2*)&h3);
    acc[0] += f0.x; acc[1] += f0.y; acc[2] += f1.x; acc[3] += f1.y;
    acc[4] += f2.x; acc[5] += f2.y; acc[6] += f3.x; acc[7] += f3.y;
}

// ---------------- CSR build ----------------
__global__ void k_zero(int n) {
    int i = blockIdx.x * blockDim.x + threadIdx.x;
    if (i < n) g_deg[i] = 0;
    if (i < SCAN_NB) g_pack[i] = 0ULL;
}

// count + record rank of each edge within its dst
__global__ void k_count(const int* __restrict__ ei, int E) {
    int e = blockIdx.x * blockDim.x + threadIdx.x;
    if (e < E) g_rank[e] = (unsigned char)atomicAdd(&g_deg[ei[E + e]], 1);
}

// vectorized: 4 dsts per thread (requires E % 4 == 0); ei pre-offset to dst half
__global__ void k_count4(const int* __restrict__ ei, int E4) {
    int e = blockIdx.x * blockDim.x + threadIdx.x;
    if (e < E4) {
        int4 d = ((const int4*)ei)[e];
        unsigned char r0 = (unsigned char)atomicAdd(&g_deg[d.x], 1);
        unsigned char r1 = (unsigned char)atomicAdd(&g_deg[d.y], 1);
        unsigned char r2 = (unsigned char)atomicAdd(&g_deg[d.z], 1);
        unsigned char r3 = (unsigned char)atomicAdd(&g_deg[d.w], 1);
        ((uchar4*)g_rank)[e] = make_uchar4(r0, r1, r2, r3);
    }
}

// ---- fused single-pass exclusive scan (decoupled lookback) + dinv + t0 ----
__global__ __launch_bounds__(SCAN_TPB) void k_scanf(const float* __restrict__ x, int n, int E) {
    __shared__ int sd[SCAN_TPB];
    int t = threadIdx.x;
    int b = blockIdx.x;
    int i = b * SCAN_TPB + t;
    int v = (i < n) ? g_deg[i] : 0;
    sd[t] = v;
    __syncthreads();
    for (int off = 1; off < SCAN_TPB; off <<= 1) {
        int y = (t >= off) ? sd[t - off] : 0;
        __syncthreads();
        sd[t] += y;
        __syncthreads();
    }
    int incl = sd[t];
    if (t == SCAN_TPB - 1) {
        unsigned long long p = (1ULL << 63) | (unsigned long long)(unsigned)incl;
        *((volatile unsigned long long*)&g_pack[b]) = p;
    }
    int offs = 0;
    for (int p = t; p < b; p += SCAN_TPB) {
        unsigned long long w;
        do { w = *((volatile unsigned long long*)&g_pack[p]); } while (!(w >> 63));
        offs += (int)(unsigned)(w & 0xFFFFFFFFULL);
    }
    __syncthreads();
    sd[t] = offs;
    __syncthreads();
    for (int o = SCAN_TPB / 2; o > 0; o >>= 1) {
        if (t < o) sd[t] += sd[t + o];
        __syncthreads();
    }
    int blockoff = sd[0];
    if (i < n) {
        int off = blockoff + incl - v;
        g_off[i] = off;
        float dv = rsqrtf((float)(v + 1));  // +1 self loop
        g_dinv[i] = dv;
        g_t0[i] = x[i] * dv;
        if (i == 0) g_off[n] = E;
    }
}

// atomic-free fill: p = off[d] + rank[e]
__global__ void k_fill(const int* __restrict__ ei, int E) {
    int e = blockIdx.x * blockDim.x + threadIdx.x;
    if (e < E) {
        int s = ei[e];
        int d = ei[E + e];
        g_srcs[__ldg(&g_off[d]) + (int)g_rank[e]] = s;
    }
}

// vectorized: 4 edges per thread (requires E % 4 == 0)
__global__ void k_fill4(const int* __restrict__ ei, int E, int E4) {
    int e = blockIdx.x * blockDim.x + threadIdx.x;
    if (e < E4) {
        int4 s = ((const int4*)ei)[e];
        int4 d = ((const int4*)(ei + E))[e];
        uchar4 r = ((const uchar4*)g_rank)[e];
        g_srcs[__ldg(&g_off[d.x]) + (int)r.x] = s.x;
        g_srcs[__ldg(&g_off[d.y]) + (int)r.y] = s.y;
        g_srcs[__ldg(&g_off[d.z]) + (int)r.z] = s.z;
        g_srcs[__ldg(&g_off[d.w]) + (int)r.w] = s.w;
    }
}

// ---------------- layer 1: scalar agg of t0 (batch-8 MLP), then t1 = fp16(dinv*relu(a*W1+b1)) ----------------
__global__ void k_l1(const float* __restrict__ W1, const float* __restrict__ b1, int n) {
    __shared__ float sw[16], sb[16];
    if (threadIdx.x < 16) { sw[threadIdx.x] = W1[threadIdx.x]; sb[threadIdx.x] = b1[threadIdx.x]; }
    __syncthreads();
    int v = blockIdx.x * blockDim.x + threadIdx.x;
    if (v >= n) return;
    float a = g_t0[v];
    int e = g_off[v], e1 = g_off[v + 1];
    for (; e + 8 <= e1; e += 8) {
        int s0 = __ldg(&g_srcs[e + 0]);
        int s1 = __ldg(&g_srcs[e + 1]);
        int s2 = __ldg(&g_srcs[e + 2]);
        int s3 = __ldg(&g_srcs[e + 3]);
        int s4 = __ldg(&g_srcs[e + 4]);
        int s5 = __ldg(&g_srcs[e + 5]);
        int s6 = __ldg(&g_srcs[e + 6]);
        int s7 = __ldg(&g_srcs[e + 7]);
        float f0 = __ldg(&g_t0[s0]);
        float f1 = __ldg(&g_t0[s1]);
        float f2 = __ldg(&g_t0[s2]);
        float f3 = __ldg(&g_t0[s3]);
        float f4 = __ldg(&g_t0[s4]);
        float f5 = __ldg(&g_t0[s5]);
        float f6 = __ldg(&g_t0[s6]);
        float f7 = __ldg(&g_t0[s7]);
        a += ((f0 + f1) + (f2 + f3)) + ((f4 + f5) + (f6 + f7));
    }
    for (; e < e1; e++) a += __ldg(&g_t0[__ldg(&g_srcs[e])]);
    float dv = g_dinv[v];
    a *= dv;
#pragma unroll
    for (int k = 0; k < 8; k++) {
        float u0 = dv * fmaxf(fmaf(a, sw[2 * k + 0], sb[2 * k + 0]), 0.f);
        float u1 = dv * fmaxf(fmaf(a, sw[2 * k + 1], sb[2 * k + 1]), 0.f);
        g_t1[v * 8 + k] = __float22half2_rn(make_float2(u0, u1));
    }
}

// ---------------- layer-2 agg d16 fp16, batch-8 MLP: g = dinv*(t1[v] + sum t1[src]) -> bufB fp32 ----------------
__global__ void k_agg2(int n) {
    int gid = blockIdx.x * blockDim.x + threadIdx.x;
    int v = gid >> 1;
    int c = gid & 1;
    if (v >= n) return;
    const uint4* tp = (const uint4*)g_t1;
    float acc[8];
    {
        uint4 hv = tp[v * 2 + c];
        float2 f0 = __half22float2(*(const __half2*)&hv.x);
        float2 f1 = __half22float2(*(const __half2*)&hv.y);
        float2 f2 = __half22float2(*(const __half2*)&hv.z);
        float2 f3 = __half22float2(*(const __half2*)&hv.w);
        acc[0] = f0.x; acc[1] = f0.y; acc[2] = f1.x; acc[3] = f1.y;
        acc[4] = f2.x; acc[5] = f2.y; acc[6] = f3.x; acc[7] = f3.y;
    }
    int e = g_off[v], e1 = g_off[v + 1];
    for (; e + 8 <= e1; e += 8) {
        int s0 = __ldg(&g_srcs[e + 0]);
        int s1 = __ldg(&g_srcs[e + 1]);
        int s2 = __ldg(&g_srcs[e + 2]);
        int s3 = __ldg(&g_srcs[e + 3]);
        int s4 = __ldg(&g_srcs[e + 4]);
        int s5 = __ldg(&g_srcs[e + 5]);
        int s6 = __ldg(&g_srcs[e + 6]);
        int s7 = __ldg(&g_srcs[e + 7]);
        uint4 a0 = __ldg(&tp[s0 * 2 + c]);
        uint4 a1 = __ldg(&tp[s1 * 2 + c]);
        uint4 a2 = __ldg(&tp[s2 * 2 + c]);
        uint4 a3 = __ldg(&tp[s3 * 2 + c]);
        uint4 a4 = __ldg(&tp[s4 * 2 + c]);
        uint4 a5 = __ldg(&tp[s5 * 2 + c]);
        uint4 a6 = __ldg(&tp[s6 * 2 + c]);
        uint4 a7 = __ldg(&tp[s7 * 2 + c]);
        hacc8(acc, a0); hacc8(acc, a1); hacc8(acc, a2); hacc8(acc, a3);
        hacc8(acc, a4); hacc8(acc, a5); hacc8(acc, a6); hacc8(acc, a7);
    }
    for (; e < e1; e++) {
        int s = __ldg(&g_srcs[e]);
        hacc8(acc, __ldg(&tp[s * 2 + c]));
    }
    float dv = g_dinv[v];
    g_bufB[v * 4 + c * 2 + 0] = make_float4(acc[0] * dv, acc[1] * dv, acc[2] * dv, acc[3] * dv);
    g_bufB[v * 4 + c * 2 + 1] = make_float4(acc[4] * dv, acc[5] * dv, acc[6] * dv, acc[7] * dv);
}

// ---------------- fused W2 + relu + W3 + dinv, HFMA2 W3 stage: g(d16) -> t3(d64 fp8 e4m3) ----------------
__global__ __launch_bounds__(128) void k_t23(const float* __restrict__ W2,
                                             const float* __restrict__ b2,
                                             const float* __restrict__ W3, int n) {
    __shared__ float   sW2[16 * 64];
    __shared__ __half2 sW3h[64 * 32];   // [i][jp]: (W3[i][2jp], W3[i][2jp+1]); 8 KB
    __shared__ float   sb2[64];
    int t = threadIdx.x;
    for (int i = t; i < 16 * 64; i += blockDim.x) sW2[i] = W2[i];
    for (int idx = t; idx < 64 * 32; idx += blockDim.x) {
        int i = idx >> 5, jp = idx & 31;
        sW3h[idx] = __floats2half2_rn(W3[i * 64 + 2 * jp], W3[i * 64 + 2 * jp + 1]);
    }
    if (t < 64) sb2[t] = b2[t];
    __syncthreads();
    int v = blockIdx.x * blockDim.x + t;
    if (v >= n) return;
    float g[16];
#pragma unroll
    for (int j = 0; j < 4; j++) {
        float4 gg = g_bufB[v * 4 + j];
        g[4 * j] = gg.x; g[4 * j + 1] = gg.y; g[4 * j + 2] = gg.z; g[4 * j + 3] = gg.w;
    }
    float2 zf[32];
#pragma unroll
    for (int j = 0; j < 32; j++) zf[j] = make_float2(0.f, 0.f);
#pragma unroll
    for (int ch = 0; ch < 4; ch++) {
        float4 a[4];
#pragma unroll
        for (int q = 0; q < 4; q++) a[q] = ((const float4*)sb2)[ch * 4 + q];
#pragma unroll
        for (int k = 0; k < 16; k++) {
            float gk = g[k];
            const float4* wk = (const float4*)&sW2[k * 64 + ch * 16];
#pragma unroll
            for (int q = 0; q < 4; q++) {
                float4 w = wk[q];
                a[q].x = fmaf(gk, w.x, a[q].x); a[q].y = fmaf(gk, w.y, a[q].y);
                a[q].z = fmaf(gk, w.z, a[q].z); a[q].w = fmaf(gk, w.w, a[q].w);
            }
        }
        __half2 yb[16];
#pragma unroll
        for (int q = 0; q < 4; q++) {
            yb[4 * q + 0] = __float2half2_rn(fmaxf(a[q].x, 0.f));
            yb[4 * q + 1] = __float2half2_rn(fmaxf(a[q].y, 0.f));
            yb[4 * q + 2] = __float2half2_rn(fmaxf(a[q].z, 0.f));
            yb[4 * q + 3] = __float2half2_rn(fmaxf(a[q].w, 0.f));
        }
        __half2 zh[32];
        __half2 hz = __float2half2_rn(0.f);
#pragma unroll
        for (int j = 0; j < 32; j++) zh[j] = hz;
#pragma unroll
        for (int ii = 0; ii < 16; ii++) {
            const uint4* wr4 = (const uint4*)&sW3h[(ch * 16 + ii) * 32];
            __half2 yv = yb[ii];
#pragma unroll
            for (int jq = 0; jq < 8; jq++) {
                uint4 w = wr4[jq];
                zh[jq * 4 + 0] = __hfma2(yv, *(const __half2*)&w.x, zh[jq * 4 + 0]);
                zh[jq * 4 + 1] = __hfma2(yv, *(const __half2*)&w.y, zh[jq * 4 + 1]);
                zh[jq * 4 + 2] = __hfma2(yv, *(const __half2*)&w.z, zh[jq * 4 + 2]);
                zh[jq * 4 + 3] = __hfma2(yv, *(const __half2*)&w.w, zh[jq * 4 + 3]);
            }
        }
#pragma unroll
        for (int j = 0; j < 32; j++) {
            float2 f = __half22float2(zh[j]);
            zf[j].x += f.x; zf[j].y += f.y;
        }
    }
    float dv = g_dinv[v];
#pragma unroll
    for (int j = 0; j < 16; j++) {
        float2 lo = make_float2(zf[2 * j].x * dv,     zf[2 * j].y * dv);
        float2 hi = make_float2(zf[2 * j + 1].x * dv, zf[2 * j + 1].y * dv);
        unsigned int plo = (unsigned int)__nv_cvt_float2_to_fp8x2(lo, __NV_SATFINITE, __NV_E4M3);
        unsigned int phi = (unsigned int)__nv_cvt_float2_to_fp8x2(hi, __NV_SATFINITE, __NV_E4M3);
        g_bufF[v * 16 + j] = plo | (phi << 16);
    }
}

// ---------------- d=64 fp8 agg (batch-8 MLP) + b3 + relu + W4 + group reduce + dinv ----------------
// 8 lanes per node; lane c owns fp8 values [8c, 8c+8) = one uint2 (8 B). Row = 64 B.
__global__ void k_agg3w4(const float* __restrict__ b3, const float* __restrict__ W4, int n) {
    __shared__ float sW4[64 * 5];
    int t = threadIdx.x;
    for (int i = t; i < 64 * 5; i += blockDim.x) sW4[i] = W4[i];
    __syncthreads();
    int gid = blockIdx.x * blockDim.x + t;
    int v = gid / 8;
    int c = gid % 8;
    if (v >= n) return;

    const uint2* hp = (const uint2*)g_bufF;   // 8 uint2 per node row (64 B)
    float acc[8] = {0.f, 0.f, 0.f, 0.f, 0.f, 0.f, 0.f, 0.f};
    facc8(acc, hp[v * 8 + c]);                // self-loop term
    int e = g_off[v], e1 = g_off[v + 1];
    for (; e + 8 <= e1; e += 8) {
        int s0 = __ldg(&g_srcs[e + 0]);
        int s1 = __ldg(&g_srcs[e + 1]);
        int s2 = __ldg(&g_srcs[e + 2]);
        int s3 = __ldg(&g_srcs[e + 3]);
        int s4 = __ldg(&g_srcs[e + 4]);
        int s5 = __ldg(&g_srcs[e + 5]);
        int s6 = __ldg(&g_srcs[e + 6]);
        int s7 = __ldg(&g_srcs[e + 7]);
        uint2 a0 = __ldg(&hp[s0 * 8 + c]);
        uint2 a1 = __ldg(&hp[s1 * 8 + c]);
        uint2 a2 = __ldg(&hp[s2 * 8 + c]);
        uint2 a3 = __ldg(&hp[s3 * 8 + c]);
        uint2 a4 = __ldg(&hp[s4 * 8 + c]);
        uint2 a5 = __ldg(&hp[s5 * 8 + c]);
        uint2 a6 = __ldg(&hp[s6 * 8 + c]);
        uint2 a7 = __ldg(&hp[s7 * 8 + c]);
        facc8(acc, a0); facc8(acc, a1); facc8(acc, a2); facc8(acc, a3);
        facc8(acc, a4); facc8(acc, a5); facc8(acc, a6); facc8(acc, a7);
    }
    for (; e < e1; e++) {
        int s = __ldg(&g_srcs[e]);
        facc8(acc, __ldg(&hp[s * 8 + c]));
    }
    float dv = g_dinv[v];
    float4 bb0 = ((const float4*)b3)[2 * c];
    float4 bb1 = ((const float4*)b3)[2 * c + 1];
    float h[8];
    h[0] = fmaxf(fmaf(acc[0], dv, bb0.x), 0.f);
    h[1] = fmaxf(fmaf(acc[1], dv, bb0.y), 0.f);
    h[2] = fmaxf(fmaf(acc[2], dv, bb0.z), 0.f);
    h[3] = fmaxf(fmaf(acc[3], dv, bb0.w), 0.f);
    h[4] = fmaxf(fmaf(acc[4], dv, bb1.x), 0.f);
    h[5] = fmaxf(fmaf(acc[5], dv, bb1.y), 0.f);
    h[6] = fmaxf(fmaf(acc[6], dv, bb1.z), 0.f);
    h[7] = fmaxf(fmaf(acc[7], dv, bb1.w), 0.f);
    const float* w = &sW4[c * 8 * 5];
    float p[5];
#pragma unroll
    for (int j = 0; j < 5; j++) {
        float s = h[0] * w[j];
#pragma unroll
        for (int i = 1; i < 8; i++) s = fmaf(h[i], w[i * 5 + j], s);
        p[j] = s;
    }
    unsigned m = __activemask();
#pragma unroll
    for (int off = 4; off > 0; off >>= 1) {
#pragma unroll
        for (int j = 0; j < 5; j++) p[j] += __shfl_down_sync(m, p[j], off, 8);
    }
    if (c == 0) {
        g_bufB[v * 2 + 0] = make_float4(dv * p[0], dv * p[1], dv * p[2], dv * p[3]);
        g_bufB[v * 2 + 1] = make_float4(dv * p[4], 0.f, 0.f, 0.f);
    }
}

// ---------------- final d=5 agg (batch-4 MLP) + b4 + log_softmax ----------------
__global__ void k_final(const float* __restrict__ b4, float* __restrict__ out, int n) {
    int v = blockIdx.x * blockDim.x + threadIdx.x;
    if (v >= n) return;
    float4 a0 = g_bufB[v * 2 + 0];
    float4 a1 = g_bufB[v * 2 + 1];
    int e = g_off[v], e1 = g_off[v + 1];
    for (; e + 4 <= e1; e += 4) {
        int s0 = __ldg(&g_srcs[e + 0]);
        int s1 = __ldg(&g_srcs[e + 1]);
        int s2 = __ldg(&g_srcs[e + 2]);
        int s3 = __ldg(&g_srcs[e + 3]);
        float4 p00 = __ldg(&g_bufB[s0 * 2 + 0]);
        float4 p01 = __ldg(&g_bufB[s0 * 2 + 1]);
        float4 p10 = __ldg(&g_bufB[s1 * 2 + 0]);
        float4 p11 = __ldg(&g_bufB[s1 * 2 + 1]);
        float4 p20 = __ldg(&g_bufB[s2 * 2 + 0]);
        float4 p21 = __ldg(&g_bufB[s2 * 2 + 1]);
        float4 p30 = __ldg(&g_bufB[s3 * 2 + 0]);
        float4 p31 = __ldg(&g_bufB[s3 * 2 + 1]);
        a0.x += (p00.x + p10.x) + (p20.x + p30.x);
        a0.y += (p00.y + p10.y) + (p20.y + p30.y);
        a0.z += (p00.z + p10.z) + (p20.z + p30.z);
        a0.w += (p00.w + p10.w) + (p20.w + p30.w);
        a1.x += (p01.x + p11.x) + (p21.x + p31.x);
    }
    for (; e < e1; e++) {
        int s = __ldg(&g_srcs[e]);
        float4 t0 = __ldg(&g_bufB[s * 2 + 0]);
        float4 t1 = __ldg(&g_bufB[s * 2 + 1]);
        a0.x += t0.x; a0.y += t0.y; a0.z += t0.z; a0.w += t0.w;
        a1.x += t1.x;
    }
    float dv = g_dinv[v];
    float z[5];
    z[0] = fmaf(a0.x, dv, b4[0]);
    z[1] = fmaf(a0.y, dv, b4[1]);
    z[2] = fmaf(a0.z, dv, b4[2]);
    z[3] = fmaf(a0.w, dv, b4[3]);
    z[4] = fmaf(a1.x, dv, b4[4]);
    float mx = z[0];
#pragma unroll
    for (int j = 1; j < 5; j++) mx = fmaxf(mx, z[j]);
    float sum = 0.f;
#pragma unroll
    for (int j = 0; j < 5; j++) sum += expf(z[j] - mx);
    float l = mx + logf(sum);
#pragma unroll
    for (int j = 0; j < 5; j++) out[v * 5 + j] = z[j] - l;
}

extern "C" void kernel_launch(void* const* d_in, const int* in_sizes, int n_in,
                              void* d_out, int out_size) {
    const float* x  = (const float*)d_in[0];
    const int*   ei = (const int*)d_in[1];      // int32 (JAX x64 disabled)
    const float* W1 = (const float*)d_in[2];
    const float* b1 = (const float*)d_in[3];
    const float* W2 = (const float*)d_in[4];
    const float* b2 = (const float*)d_in[5];
    const float* W3 = (const float*)d_in[6];
    const float* b3 = (const float*)d_in[7];
    const float* W4 = (const float*)d_in[8];
    const float* b4 = (const float*)d_in[9];
    float* out = (float*)d_out;

    int N = in_sizes[0];
    int E = in_sizes[1] / 2;

    int nB  = (N + 255) / 256;
    int snb = (N + SCAN_TPB - 1) / SCAN_TPB;

    // CSR build: zero -> count(+uchar rank) -> fused scan -> atomic-free fill
    k_zero<<<nB, 256>>>(N);
    if ((E & 3) == 0) {
        int E4 = E >> 2;
        int eB4 = (E4 + 255) / 256;
        k_count4<<<eB4, 256>>>(ei + E, E4);
        k_scanf<<<snb, SCAN_TPB>>>(x, N, E);
        k_fill4<<<eB4, 256>>>(ei, E, E4);
    } else {
        int eB = (E + 255) / 256;
        k_count<<<eB, 256>>>(ei, E);
        k_scanf<<<snb, SCAN_TPB>>>(x, N, E);
        k_fill<<<eB, 256>>>(ei, E);
    }

    // Layer 1: scalar agg (batch-8) + transform (1->16), fp16 out
    k_l1<<<nB, 256>>>(W1, b1, N);
    // Layer 2 agg in d=16 fp16 (before W2), batch-8 MLP
    k_agg2<<<(N * 2 + 255) / 256, 256>>>(N);
    // Fused W2+relu+W3 node transform (fp8 e4m3 output)
    k_t23<<<(N + 127) / 128, 128>>>(W2, b2, W3, N);
    // Layer 3 agg d=64 fp8 (batch-8 MLP), fused bias/relu/W4 epilogue
    k_agg3w4<<<(N * 8 + 255) / 256, 256>>>(b3, W4, N);
    // Layer 4 agg d=5 (batch-4) + log_softmax
    k_final<<<nB, 256>>>(b4, out, N);
}

// round 17
// speedup vs baseline: 1.0990x; 1.0299x over previous
#include <cuda_runtime.h>
#include <cuda_fp16.h>
#include <cuda_fp8.h>
#include <math.h>

#define N_MAX 100000
#define E_MAX 3200000
#define SCAN_TPB 512
#define SCAN_NB ((N_MAX + SCAN_TPB - 1) / SCAN_TPB)

// ---- device scratch (allocation-free rule: static globals; zero-initialized at load) ----
__device__ int            g_deg[N_MAX];        // self-cleaned by k_scanf each launch
__device__ int            g_off[N_MAX + 1];
__device__ float          g_dinv[N_MAX];
__device__ __half         g_t0h[N_MAX];        // fp16 t0: 200 KB table (L1-resident gathers)
__device__ unsigned char  g_rank[E_MAX];       // per-edge rank within its dst
__device__ int            g_srcs[E_MAX];
__device__ __half2        g_t1[N_MAX * 8];     // fp16 t1: 16 halves/node (32 B/row)
__device__ __half2        g_gh[N_MAX * 8];     // fp16 g handoff: 16 halves/node (32 B/row)
__device__ float4         g_bufB[N_MAX * 2];   // fp32 t4 stage (d5 pad8)
__device__ unsigned int   g_bufF[N_MAX * 16];  // fp8 t3: 64 e4m3/node (64 B/row)
__device__ unsigned long long g_pack[SCAN_NB]; // decoupled-lookback; zeroed by count each launch

// accumulate a uint4 of 8 halves into fp32 acc[8]
__device__ __forceinline__ void hacc8(float* acc, uint4 hv) {
    float2 f0 = __half22float2(*(const __half2*)&hv.x);
    float2 f1 = __half22float2(*(const __half2*)&hv.y);
    float2 f2 = __half22float2(*(const __half2*)&hv.z);
    float2 f3 = __half22float2(*(const __half2*)&hv.w);
    acc[0] += f0.x; acc[1] += f0.y; acc[2] += f1.x; acc[3] += f1.y;
    acc[4] += f2.x; acc[5] += f2.y; acc[6] += f3.x; acc[7] += f3.y;
}

// accumulate a uint2 of 8 e4m3 values into fp32 acc[8]
__device__ __forceinline__ void facc8(float* acc, uint2 hv) {
    __half2_raw h0 = __nv_cvt_fp8x2_to_halfraw2((__nv_fp8x2_storage_t)(hv.x & 0xFFFF), __NV_E4M3);
    __half2_raw h1 = __nv_cvt_fp8x2_to_halfraw2((__nv_fp8x2_storage_t)(hv.x >> 16),    __NV_E4M3);
    __half2_raw h2 = __nv_cvt_fp8x2_to_halfraw2((__nv_fp8x2_storage_t)(hv.y & 0xFFFF), __NV_E4M3);
    __half2_raw h3 = __nv_cvt_fp8x2_to_halfraw2((__nv_fp8x2_storage_t)(hv.y >> 16),    __NV_E4M3);
    float2 f0 = __half22float2(*(const __half2*)&h0);
    float2 f1 = __half22float2(*(const __half2*)&h1);
    float2 f2 = __half22float2(*(const __half2*)&h2);
    float2 f3 = __half22float2(*(const __half2*)&h3);
    acc[0] += f0.x; acc[1] += f0.y; acc[2] += f1.x; acc[3] += f1.y;
    acc[4] += f2.x; acc[5] += f2.y; acc[6] += f3.x; acc[7] += f3.y;
}

// ---------------- CSR build ----------------
// count + record rank; also zero g_pack for this launch's scan (stream-ordered before k_scanf)
__global__ void k_count(const int* __restrict__ ei, int E) {
    int e = blockIdx.x * blockDim.x + threadIdx.x;
    if (e < SCAN_NB) g_pack[e] = 0ULL;
    if (e < E) g_rank[e] = (unsigned char)atomicAdd(&g_deg[ei[E + e]], 1);
}

__global__ void k_count4(const int* __restrict__ ei, int E4) {
    int e = blockIdx.x * blockDim.x + threadIdx.x;
    if (e < SCAN_NB) g_pack[e] = 0ULL;
    if (e < E4) {
        int4 d = ((const int4*)ei)[e];
        unsigned char r0 = (unsigned char)atomicAdd(&g_deg[d.x], 1);
        unsigned char r1 = (unsigned char)atomicAdd(&g_deg[d.y], 1);
        unsigned char r2 = (unsigned char)atomicAdd(&g_deg[d.z], 1);
        unsigned char r3 = (unsigned char)atomicAdd(&g_deg[d.w], 1);
        ((uchar4*)g_rank)[e] = make_uchar4(r0, r1, r2, r3);
    }
}

// ---- fused single-pass exclusive scan (decoupled lookback) + dinv + t0(fp16); self-cleans g_deg ----
__global__ __launch_bounds__(SCAN_TPB) void k_scanf(const float* __restrict__ x, int n, int E) {
    __shared__ int sd[SCAN_TPB];
    int t = threadIdx.x;
    int b = blockIdx.x;
    int i = b * SCAN_TPB + t;
    int v = (i < n) ? g_deg[i] : 0;
    sd[t] = v;
    __syncthreads();
    for (int off = 1; off < SCAN_TPB; off <<= 1) {
        int y = (t >= off) ? sd[t - off] : 0;
        __syncthreads();
        sd[t] += y;
        __syncthreads();
    }
    int incl = sd[t];
    if (t == SCAN_TPB - 1) {
        unsigned long long p = (1ULL << 63) | (unsigned long long)(unsigned)incl;
        *((volatile unsigned long long*)&g_pack[b]) = p;
    }
    int offs = 0;
    for (int p = t; p < b; p += SCAN_TPB) {
        unsigned long long w;
        do { w = *((volatile unsigned long long*)&g_pack[p]); } while (!(w >> 63));
        offs += (int)(unsigned)(w & 0xFFFFFFFFULL);
    }
    __syncthreads();
    sd[t] = offs;
    __syncthreads();
    for (int o = SCAN_TPB / 2; o > 0; o >>= 1) {
        if (t < o) sd[t] += sd[t + o];
        __syncthreads();
    }
    int blockoff = sd[0];
    if (i < n) {
        int off = blockoff + incl - v;
        g_off[i] = off;
        float dv = rsqrtf((float)(v + 1));  // +1 self loop
        g_dinv[i] = dv;
        g_t0h[i] = __float2half_rn(x[i] * dv);
        g_deg[i] = 0;                       // self-clean for next launch
        if (i == 0) g_off[n] = E;
    }
}

// atomic-free fill: p = off[d] + rank[e]
__global__ void k_fill(const int* __restrict__ ei, int E) {
    int e = blockIdx.x * blockDim.x + threadIdx.x;
    if (e < E) {
        int s = ei[e];
        int d = ei[E + e];
        g_srcs[__ldg(&g_off[d]) + (int)g_rank[e]] = s;
    }
}

__global__ void k_fill4(const int* __restrict__ ei, int E, int E4) {
    int e = blockIdx.x * blockDim.x + threadIdx.x;
    if (e < E4) {
        int4 s = ((const int4*)ei)[e];
        int4 d = ((const int4*)(ei + E))[e];
        uchar4 r = ((const uchar4*)g_rank)[e];
        g_srcs[__ldg(&g_off[d.x]) + (int)r.x] = s.x;
        g_srcs[__ldg(&g_off[d.y]) + (int)r.y] = s.y;
        g_srcs[__ldg(&g_off[d.z]) + (int)r.z] = s.z;
        g_srcs[__ldg(&g_off[d.w]) + (int)r.w] = s.w;
    }
}

// ---------------- layer 1: fp16 scalar agg of t0 (batch-8 MLP), then t1 = fp16(dinv*relu(a*W1+b1)) ----------------
__global__ void k_l1(const float* __restrict__ W1, const float* __restrict__ b1, int n) {
    __shared__ float sw[16], sb[16];
    if (threadIdx.x < 16) { sw[threadIdx.x] = W1[threadIdx.x]; sb[threadIdx.x] = b1[threadIdx.x]; }
    __syncthreads();
    int v = blockIdx.x * blockDim.x + threadIdx.x;
    if (v >= n) return;
    float a = __half2float(g_t0h[v]);
    int e = g_off[v], e1 = g_off[v + 1];
    for (; e + 8 <= e1; e += 8) {
        int s0 = __ldg(&g_srcs[e + 0]);
        int s1 = __ldg(&g_srcs[e + 1]);
        int s2 = __ldg(&g_srcs[e + 2]);
        int s3 = __ldg(&g_srcs[e + 3]);
        int s4 = __ldg(&g_srcs[e + 4]);
        int s5 = __ldg(&g_srcs[e + 5]);
        int s6 = __ldg(&g_srcs[e + 6]);
        int s7 = __ldg(&g_srcs[e + 7]);
        float f0 = __half2float(__ldg(&g_t0h[s0]));
        float f1 = __half2float(__ldg(&g_t0h[s1]));
        float f2 = __half2float(__ldg(&g_t0h[s2]));
        float f3 = __half2float(__ldg(&g_t0h[s3]));
        float f4 = __half2float(__ldg(&g_t0h[s4]));
        float f5 = __half2float(__ldg(&g_t0h[s5]));
        float f6 = __half2float(__ldg(&g_t0h[s6]));
        float f7 = __half2float(__ldg(&g_t0h[s7]));
        a += ((f0 + f1) + (f2 + f3)) + ((f4 + f5) + (f6 + f7));
    }
    for (; e < e1; e++) a += __half2float(__ldg(&g_t0h[__ldg(&g_srcs[e])]));
    float dv = g_dinv[v];
    a *= dv;
#pragma unroll
    for (int k = 0; k < 8; k++) {
        float u0 = dv * fmaxf(fmaf(a, sw[2 * k + 0], sb[2 * k + 0]), 0.f);
        float u1 = dv * fmaxf(fmaf(a, sw[2 * k + 1], sb[2 * k + 1]), 0.f);
        g_t1[v * 8 + k] = __float22half2_rn(make_float2(u0, u1));
    }
}

// ---------------- layer-2 agg d16 fp16, batch-8 MLP: g = dinv*(t1[v] + sum t1[src]) -> g_gh fp16 ----------------
__global__ void k_agg2(int n) {
    int gid = blockIdx.x * blockDim.x + threadIdx.x;
    int v = gid >> 1;
    int c = gid & 1;
    if (v >= n) return;
    const uint4* tp = (const uint4*)g_t1;
    float acc[8];
    {
        uint4 hv = tp[v * 2 + c];
        float2 f0 = __half22float2(*(const __half2*)&hv.x);
        float2 f1 = __half22float2(*(const __half2*)&hv.y);
        float2 f2 = __half22float2(*(const __half2*)&hv.z);
        float2 f3 = __half22float2(*(const __half2*)&hv.w);
        acc[0] = f0.x; acc[1] = f0.y; acc[2] = f1.x; acc[3] = f1.y;
        acc[4] = f2.x; acc[5] = f2.y; acc[6] = f3.x; acc[7] = f3.y;
    }
    int e = g_off[v], e1 = g_off[v + 1];
    for (; e + 8 <= e1; e += 8) {
        int s0 = __ldg(&g_srcs[e + 0]);
        int s1 = __ldg(&g_srcs[e + 1]);
        int s2 = __ldg(&g_srcs[e + 2]);
        int s3 = __ldg(&g_srcs[e + 3]);
        int s4 = __ldg(&g_srcs[e + 4]);
        int s5 = __ldg(&g_srcs[e + 5]);
        int s6 = __ldg(&g_srcs[e + 6]);
        int s7 = __ldg(&g_srcs[e + 7]);
        uint4 a0 = __ldg(&tp[s0 * 2 + c]);
        uint4 a1 = __ldg(&tp[s1 * 2 + c]);
        uint4 a2 = __ldg(&tp[s2 * 2 + c]);
        uint4 a3 = __ldg(&tp[s3 * 2 + c]);
        uint4 a4 = __ldg(&tp[s4 * 2 + c]);
        uint4 a5 = __ldg(&tp[s5 * 2 + c]);
        uint4 a6 = __ldg(&tp[s6 * 2 + c]);
        uint4 a7 = __ldg(&tp[s7 * 2 + c]);
        hacc8(acc, a0); hacc8(acc, a1); hacc8(acc, a2); hacc8(acc, a3);
        hacc8(acc, a4); hacc8(acc, a5); hacc8(acc, a6); hacc8(acc, a7);
    }
    for (; e < e1; e++) {
        int s = __ldg(&g_srcs[e]);
        hacc8(acc, __ldg(&tp[s * 2 + c]));
    }
    float dv = g_dinv[v];
#pragma unroll
    for (int k = 0; k < 4; k++)
        g_gh[v * 8 + c * 4 + k] =
            __float22half2_rn(make_float2(acc[2 * k] * dv, acc[2 * k + 1] * dv));
}

// ---------------- fused W2 + relu + W3 + dinv, HFMA2 W3 stage: g(d16 fp16) -> t3(d64 fp8 e4m3) ----------------
__global__ __launch_bounds__(128) void k_t23(const float* __restrict__ W2,
                                             const float* __restrict__ b2,
                                             const float* __restrict__ W3, int n) {
    __shared__ float   sW2[16 * 64];
    __shared__ __half2 sW3h[64 * 32];   // 8 KB
    __shared__ float   sb2[64];
    int t = threadIdx.x;
    for (int i = t; i < 16 * 64; i += blockDim.x) sW2[i] = W2[i];
    for (int idx = t; idx < 64 * 32; idx += blockDim.x) {
        int i = idx >> 5, jp = idx & 31;
        sW3h[idx] = __floats2half2_rn(W3[i * 64 + 2 * jp], W3[i * 64 + 2 * jp + 1]);
    }
    if (t < 64) sb2[t] = b2[t];
    __syncthreads();
    int v = blockIdx.x * blockDim.x + t;
    if (v >= n) return;
    float g[16];
    {
        const uint4* gp = (const uint4*)g_gh;   // 2 uint4 per node row (32 B)
        uint4 ha = gp[v * 2 + 0];
        uint4 hb = gp[v * 2 + 1];
        float2 f;
        f = __half22float2(*(const __half2*)&ha.x); g[0] = f.x;  g[1] = f.y;
        f = __half22float2(*(const __half2*)&ha.y); g[2] = f.x;  g[3] = f.y;
        f = __half22float2(*(const __half2*)&ha.z); g[4] = f.x;  g[5] = f.y;
        f = __half22float2(*(const __half2*)&ha.w); g[6] = f.x;  g[7] = f.y;
        f = __half22float2(*(const __half2*)&hb.x); g[8] = f.x;  g[9] = f.y;
        f = __half22float2(*(const __half2*)&hb.y); g[10] = f.x; g[11] = f.y;
        f = __half22float2(*(const __half2*)&hb.z); g[12] = f.x; g[13] = f.y;
        f = __half22float2(*(const __half2*)&hb.w); g[14] = f.x; g[15] = f.y;
    }
    float2 zf[32];
#pragma unroll
    for (int j = 0; j < 32; j++) zf[j] = make_float2(0.f, 0.f);
#pragma unroll
    for (int ch = 0; ch < 4; ch++) {
        float4 a[4];
#pragma unroll
        for (int q = 0; q < 4; q++) a[q] = ((const float4*)sb2)[ch * 4 + q];
#pragma unroll
        for (int k = 0; k < 16; k++) {
            float gk = g[k];
            const float4* wk = (const float4*)&sW2[k * 64 + ch * 16];
#pragma unroll
            for (int q = 0; q < 4; q++) {
                float4 w = wk[q];
                a[q].x = fmaf(gk, w.x, a[q].x); a[q].y = fmaf(gk, w.y, a[q].y);
                a[q].z = fmaf(gk, w.z, a[q].z); a[q].w = fmaf(gk, w.w, a[q].w);
            }
        }
        __half2 yb[16];
#pragma unroll
        for (int q = 0; q < 4; q++) {
            yb[4 * q + 0] = __float2half2_rn(fmaxf(a[q].x, 0.f));
            yb[4 * q + 1] = __float2half2_rn(fmaxf(a[q].y, 0.f));
            yb[4 * q + 2] = __float2half2_rn(fmaxf(a[q].z, 0.f));
            yb[4 * q + 3] = __float2half2_rn(fmaxf(a[q].w, 0.f));
        }
        __half2 zh[32];
        __half2 hz = __float2half2_rn(0.f);
#pragma unroll
        for (int j = 0; j < 32; j++) zh[j] = hz;
#pragma unroll
        for (int ii = 0; ii < 16; ii++) {
            const uint4* wr4 = (const uint4*)&sW3h[(ch * 16 + ii) * 32];
            __half2 yv = yb[ii];
#pragma unroll
            for (int jq = 0; jq < 8; jq++) {
                uint4 w = wr4[jq];
                zh[jq * 4 + 0] = __hfma2(yv, *(const __half2*)&w.x, zh[jq * 4 + 0]);
                zh[jq * 4 + 1] = __hfma2(yv, *(const __half2*)&w.y, zh[jq * 4 + 1]);
                zh[jq * 4 + 2] = __hfma2(yv, *(const __half2*)&w.z, zh[jq * 4 + 2]);
                zh[jq * 4 + 3] = __hfma2(yv, *(const __half2*)&w.w, zh[jq * 4 + 3]);
            }
        }
#pragma unroll
        for (int j = 0; j < 32; j++) {
            float2 f = __half22float2(zh[j]);
            zf[j].x += f.x; zf[j].y += f.y;
        }
    }
    float dv = g_dinv[v];
#pragma unroll
    for (int j = 0; j < 16; j++) {
        float2 lo = make_float2(zf[2 * j].x * dv,     zf[2 * j].y * dv);
        float2 hi = make_float2(zf[2 * j + 1].x * dv, zf[2 * j + 1].y * dv);
        unsigned int plo = (unsigned int)__nv_cvt_float2_to_fp8x2(lo, __NV_SATFINITE, __NV_E4M3);
        unsigned int phi = (unsigned int)__nv_cvt_float2_to_fp8x2(hi, __NV_SATFINITE, __NV_E4M3);
        g_bufF[v * 16 + j] = plo | (phi << 16);
    }
}

// ---------------- d=64 fp8 agg (batch-8 MLP) + b3 + relu + W4 + group reduce + dinv ----------------
__global__ void k_agg3w4(const float* __restrict__ b3, const float* __restrict__ W4, int n) {
    __shared__ float sW4[64 * 5];
    int t = threadIdx.x;
    for (int i = t; i < 64 * 5; i += blockDim.x) sW4[i] = W4[i];
    __syncthreads();
    int gid = blockIdx.x * blockDim.x + t;
    int v = gid / 8;
    int c = gid % 8;
    if (v >= n) return;

    const uint2* hp = (const uint2*)g_bufF;   // 8 uint2 per node row (64 B)
    float acc[8] = {0.f, 0.f, 0.f, 0.f, 0.f, 0.f, 0.f, 0.f};
    facc8(acc, hp[v * 8 + c]);                // self-loop term
    int e = g_off[v], e1 = g_off[v + 1];
    for (; e + 8 <= e1; e += 8) {
        int s0 = __ldg(&g_srcs[e + 0]);
        int s1 = __ldg(&g_srcs[e + 1]);
        int s2 = __ldg(&g_srcs[e + 2]);
        int s3 = __ldg(&g_srcs[e + 3]);
        int s4 = __ldg(&g_srcs[e + 4]);
        int s5 = __ldg(&g_srcs[e + 5]);
        int s6 = __ldg(&g_srcs[e + 6]);
        int s7 = __ldg(&g_srcs[e + 7]);
        uint2 a0 = __ldg(&hp[s0 * 8 + c]);
        uint2 a1 = __ldg(&hp[s1 * 8 + c]);
        uint2 a2 = __ldg(&hp[s2 * 8 + c]);
        uint2 a3 = __ldg(&hp[s3 * 8 + c]);
        uint2 a4 = __ldg(&hp[s4 * 8 + c]);
        uint2 a5 = __ldg(&hp[s5 * 8 + c]);
        uint2 a6 = __ldg(&hp[s6 * 8 + c]);
        uint2 a7 = __ldg(&hp[s7 * 8 + c]);
        facc8(acc, a0); facc8(acc, a1); facc8(acc, a2); facc8(acc, a3);
        facc8(acc, a4); facc8(acc, a5); facc8(acc, a6); facc8(acc, a7);
    }
    for (; e < e1; e++) {
        int s = __ldg(&g_srcs[e]);
        facc8(acc, __ldg(&hp[s * 8 + c]));
    }
    float dv = g_dinv[v];
    float4 bb0 = ((const float4*)b3)[2 * c];
    float4 bb1 = ((const float4*)b3)[2 * c + 1];
    float h[8];
    h[0] = fmaxf(fmaf(acc[0], dv, bb0.x), 0.f);
    h[1] = fmaxf(fmaf(acc[1], dv, bb0.y), 0.f);
    h[2] = fmaxf(fmaf(acc[2], dv, bb0.z), 0.f);
    h[3] = fmaxf(fmaf(acc[3], dv, bb0.w), 0.f);
    h[4] = fmaxf(fmaf(acc[4], dv, bb1.x), 0.f);
    h[5] = fmaxf(fmaf(acc[5], dv, bb1.y), 0.f);
    h[6] = fmaxf(fmaf(acc[6], dv, bb1.z), 0.f);
    h[7] = fmaxf(fmaf(acc[7], dv, bb1.w), 0.f);
    const float* w = &sW4[c * 8 * 5];
    float p[5];
#pragma unroll
    for (int j = 0; j < 5; j++) {
        float s = h[0] * w[j];
#pragma unroll
        for (int i = 1; i < 8; i++) s = fmaf(h[i], w[i * 5 + j], s);
        p[j] = s;
    }
    unsigned m = __activemask();
#pragma unroll
    for (int off = 4; off > 0; off >>= 1) {
#pragma unroll
        for (int j = 0; j < 5; j++) p[j] += __shfl_down_sync(m, p[j], off, 8);
    }
    if (c == 0) {
        g_bufB[v * 2 + 0] = make_float4(dv * p[0], dv * p[1], dv * p[2], dv * p[3]);
        g_bufB[v * 2 + 1] = make_float4(dv * p[4], 0.f, 0.f, 0.f);
    }
}

// ---------------- final d=5 agg (batch-4 MLP) + b4 + log_softmax ----------------
__global__ void k_final(const float* __restrict__ b4, float* __restrict__ out, int n) {
    int v = blockIdx.x * blockDim.x + threadIdx.x;
    if (v >= n) return;
    float4 a0 = g_bufB[v * 2 + 0];
    float4 a1 = g_bufB[v * 2 + 1];
    int e = g_off[v], e1 = g_off[v + 1];
    for (; e + 4 <= e1; e += 4) {
        int s0 = __ldg(&g_srcs[e + 0]);
        int s1 = __ldg(&g_srcs[e + 1]);
        int s2 = __ldg(&g_srcs[e + 2]);
        int s3 = __ldg(&g_srcs[e + 3]);
        float4 p00 = __ldg(&g_bufB[s0 * 2 + 0]);
        float4 p01 = __ldg(&g_bufB[s0 * 2 + 1]);
        float4 p10 = __ldg(&g_bufB[s1 * 2 + 0]);
        float4 p11 = __ldg(&g_bufB[s1 * 2 + 1]);
        float4 p20 = __ldg(&g_bufB[s2 * 2 + 0]);
        float4 p21 = __ldg(&g_bufB[s2 * 2 + 1]);
        float4 p30 = __ldg(&g_bufB[s3 * 2 + 0]);
        float4 p31 = __ldg(&g_bufB[s3 * 2 + 1]);
        a0.x += (p00.x + p10.x) + (p20.x + p30.x);
        a0.y += (p00.y + p10.y) + (p20.y + p30.y);
        a0.z += (p00.z + p10.z) + (p20.z + p30.z);
        a0.w += (p00.w + p10.w) + (p20.w + p30.w);
        a1.x += (p01.x + p11.x) + (p21.x + p31.x);
    }
    for (; e < e1; e++) {
        int s = __ldg(&g_srcs[e]);
        float4 t0 = __ldg(&g_bufB[s * 2 + 0]);
        float4 t1 = __ldg(&g_bufB[s * 2 + 1]);
        a0.x += t0.x; a0.y += t0.y; a0.z += t0.z; a0.w += t0.w;
        a1.x += t1.x;
    }
    float dv = g_dinv[v];
    float z[5];
    z[0] = fmaf(a0.x, dv, b4[0]);
    z[1] = fmaf(a0.y, dv, b4[1]);
    z[2] = fmaf(a0.z, dv, b4[2]);
    z[3] = fmaf(a0.w, dv, b4[3]);
    z[4] = fmaf(a1.x, dv, b4[4]);
    float mx = z[0];
#pragma unroll
    for (int j = 1; j < 5; j++) mx = fmaxf(mx, z[j]);
    float sum = 0.f;
#pragma unroll
    for (int j = 0; j < 5; j++) sum += expf(z[j] - mx);
    float l = mx + logf(sum);
#pragma unroll
    for (int j = 0; j < 5; j++) out[v * 5 + j] = z[j] - l;
}

extern "C" void kernel_launch(void* const* d_in, const int* in_sizes, int n_in,
                              void* d_out, int out_size) {
    const float* x  = (const float*)d_in[0];
    const int*   ei = (const int*)d_in[1];      // int32 (JAX x64 disabled)
    const float* W1 = (const float*)d_in[2];
    const float* b1 = (const float*)d_in[3];
    const float* W2 = (const float*)d_in[4];
    const float* b2 = (const float*)d_in[5];
    const float* W3 = (const float*)d_in[6];
    const float* b3 = (const float*)d_in[7];
    const float* W4 = (const float*)d_in[8];
    const float* b4 = (const float*)d_in[9];
    float* out = (float*)d_out;

    int N = in_sizes[0];
    int E = in_sizes[1] / 2;

    int nB  = (N + 255) / 256;
    int snb = (N + SCAN_TPB - 1) / SCAN_TPB;

    // CSR build (no zero pass: statics are load-zeroed; deg self-cleans in scanf, pack in count)
    if ((E & 3) == 0) {
        int E4 = E >> 2;
        int eB4 = (E4 + 255) / 256;
        k_count4<<<eB4, 256>>>(ei + E, E4);
        k_scanf<<<snb, SCAN_TPB>>>(x, N, E);
        k_fill4<<<eB4, 256>>>(ei, E, E4);
    } else {
        int eB = (E + 255) / 256;
        k_count<<<eB, 256>>>(ei, E);
        k_scanf<<<snb, SCAN_TPB>>>(x, N, E);
        k_fill<<<eB, 256>>>(ei, E);
    }

    // Layer 1: fp16 scalar agg (batch-8) + transform (1->16), fp16 out
    k_l1<<<nB, 256>>>(W1, b1, N);
    // Layer 2 agg in d=16 fp16 (before W2), batch-8 MLP, fp16 out
    k_agg2<<<(N * 2 + 255) / 256, 256>>>(N);
    // Fused W2+relu+W3 node transform (fp8 e4m3 output)
    k_t23<<<(N + 127) / 128, 128>>>(W2, b2, W3, N);
    // Layer 3 agg d=64 fp8 (batch-8 MLP), fused bias/relu/W4 epilogue
    k_agg3w4<<<(N * 8 + 255) / 256, 256>>>(b3, W4, N);
    // Layer 4 agg d=5 (batch-4) + log_softmax
    k_final<<<nB, 256>>>(b4, out, N);
}